// round 1
// baseline (speedup 1.0000x reference)
#include <cuda_runtime.h>
#include <cuda_bf16.h>

// ---------------------------------------------------------------------------
// Real solid harmonics (RSHxyz), max_l = 6, N points -> [N, 49] fp32.
//
// Strategy: the (dst, clm, px, py, pz) term table is a pure function of
// max_l. We regenerate it at COMPILE TIME with constexpr code replicating the
// reference generator exactly, then fully unroll the 188-term polynomial via
// template recursion so every coefficient is an immediate and every power
// lookup is a constant register reference. Per-point results are staged in
// shared memory ([BS][49], stride 49 coprime with 32 -> bank-conflict-free)
// and flushed coalesced with float4 stores.
// ---------------------------------------------------------------------------

#define HDC __host__ __device__ constexpr

constexpr int MAXL = 6;
constexpr int NOUT = (MAXL + 1) * (MAXL + 1);   // 49
constexpr int TMAX = 188;                       // term count for max_l = 6
constexpr int BS   = 128;                       // block size (points per block)

struct Tables {
    int   dst[TMAX + 1];
    float clm[TMAX + 1];
    int   px[TMAX + 1], py[TMAX + 1], pz[TMAX + 1];
    int   count;
};

HDC double cfact(int n) { double r = 1.0; for (int i = 2; i <= n; i++) r *= (double)i; return r; }
HDC double ccomb(int n, int k) {
    return (k < 0 || k > n) ? 0.0 : cfact(n) / (cfact(k) * cfact(n - k));
}

// Exact replica of the reference _build_coeffs loop structure (order matters
// only for the contiguity of equal-dst runs, which this preserves: dst is
// monotone non-decreasing).
HDC Tables build_tables() {
    Tables tb{};
    int idx = 0;
    for (int l = 0; l <= MAXL; l++) {
        for (int m = -l; m <= l; m++) {
            int am  = (m < 0) ? -m : m;
            int v2s = (m < 0) ? 1 : 0;
            int v2e = 2 * ((m < 0) ? ((am - 1) / 2) : (am / 2)) + v2s;
            for (int t = 0; t <= (l - am) / 2; t++) {
                for (int u = 0; u <= t; u++) {
                    for (int v2 = v2s; v2 <= v2e; v2 += 2) {
                        int par = (t + (v2 - v2s) / 2) & 1;
                        double c = par ? -1.0 : 1.0;
                        for (int q = 0; q < t; q++) c *= 0.25;
                        c *= ccomb(l, t);
                        c *= (am + t <= l - t) ? ccomb(l - t, am + t) : 0.0;
                        c *= ccomb(t, u);
                        c *= (v2 <= am) ? ccomb(am, v2) : 0.0;
                        tb.dst[idx] = l * (l + 1) + m;
                        tb.clm[idx] = (float)c;
                        tb.px[idx]  = 2 * t + am - 2 * u - v2;
                        tb.py[idx]  = 2 * u + v2;
                        tb.pz[idx]  = l - 2 * t - am;
                        idx++;
                    }
                }
            }
        }
    }
    tb.count = idx;
    return tb;
}

static_assert(build_tables().count == TMAX, "term count mismatch for max_l=6");

struct TermInfo { int d, px, py, pz; float c; bool last; };

HDC TermInfo term_at(int t) {
    Tables tb = build_tables();
    TermInfo r{};
    r.d  = tb.dst[t];
    r.c  = tb.clm[t];
    r.px = tb.px[t];
    r.py = tb.py[t];
    r.pz = tb.pz[t];
    r.last = (t + 1 >= tb.count) || (tb.dst[t + 1] != tb.dst[t]);
    return r;
}

// ---------------------------------------------------------------------------
// Fully-unrolled term evaluation. All indices and coefficients fold to
// compile-time constants; xs/ys/zs stay in registers.
// ---------------------------------------------------------------------------
template <int t>
__device__ __forceinline__ void eval_terms(const float (&xs)[MAXL + 1],
                                           const float (&ys)[MAXL + 1],
                                           const float (&zs)[MAXL + 1],
                                           float& acc,
                                           float* __restrict__ row_buf,
                                           const float* __restrict__ sns) {
    if constexpr (t < TMAX) {
        constexpr TermInfo TI = term_at(t);
        acc = fmaf(TI.c, xs[TI.px] * ys[TI.py] * zs[TI.pz], acc);
        if constexpr (TI.last) {
            row_buf[TI.d] = acc * sns[TI.d];
            acc = 0.0f;
        }
        eval_terms<t + 1>(xs, ys, zs, acc, row_buf, sns);
    }
}

__global__ void __launch_bounds__(BS)
rsh_fast_kernel(const float* __restrict__ xyz,
                const float* __restrict__ ns,
                float* __restrict__ out, int N) {
    __shared__ __align__(16) float sbuf[BS * NOUT];
    __shared__ float sns[NOUT];

    const int tid = threadIdx.x;
    if (tid < NOUT) sns[tid] = ns[tid];
    __syncthreads();

    const int base = blockIdx.x * BS;
    const int i = base + tid;

    float x = 0.0f, y = 0.0f, z = 0.0f;
    if (i < N) {
        x = xyz[3 * i + 0];
        y = xyz[3 * i + 1];
        z = xyz[3 * i + 2];
    }

    // Power tables built by repeated multiply (matches reference _pow_table,
    // including (-x)^0 == 1 and 0^0 == 1 exactly).
    float xs[MAXL + 1], ys[MAXL + 1], zs[MAXL + 1];
    xs[0] = 1.0f; ys[0] = 1.0f; zs[0] = 1.0f;
#pragma unroll
    for (int k = 1; k <= MAXL; k++) {
        xs[k] = xs[k - 1] * x;
        ys[k] = ys[k - 1] * y;
        zs[k] = zs[k - 1] * z;
    }

    float acc = 0.0f;
    // Row stride NOUT=49 is coprime with 32 -> bank-conflict-free stores.
    eval_terms<0>(xs, ys, zs, acc, sbuf + tid * NOUT, sns);

    __syncthreads();

    // Coalesced flush of this block's contiguous output region.
    int valid = N - base;
    if (valid > BS) valid = BS;
    const int total = valid * NOUT;            // always divisible by... handled below
    float* gout = out + (size_t)base * NOUT;   // 16B-aligned: 25088*bid bytes

    const int total4 = total >> 2;
    const float4* s4 = reinterpret_cast<const float4*>(sbuf);
    float4* g4 = reinterpret_cast<float4*>(gout);
    for (int k = tid; k < total4; k += BS) g4[k] = s4[k];
    for (int k = (total4 << 2) + tid; k < total; k += BS) gout[k] = sbuf[k];
}

// ---------------------------------------------------------------------------
// Generic fallback (used only if the runtime shapes don't match max_l=6).
// Slow but correct; reads the provided tables directly.
// ---------------------------------------------------------------------------
__global__ void rsh_generic_kernel(const float* __restrict__ xyz,
                                   const float* __restrict__ clm,
                                   const float* __restrict__ ns,
                                   const int* __restrict__ dst,
                                   const int* __restrict__ px,
                                   const int* __restrict__ py,
                                   const int* __restrict__ pz,
                                   float* __restrict__ out,
                                   int N, int T, int nout) {
    int i = blockIdx.x * blockDim.x + threadIdx.x;
    if (i >= N) return;
    float x = xyz[3 * i + 0], y = xyz[3 * i + 1], z = xyz[3 * i + 2];
    float* row = out + (size_t)i * nout;
    for (int j = 0; j < nout; j++) row[j] = 0.0f;
    for (int t = 0; t < T; t++) {
        float m = clm[t];
        int a = px[t], b = py[t], c = pz[t];
        for (int k = 0; k < a; k++) m *= x;
        for (int k = 0; k < b; k++) m *= y;
        for (int k = 0; k < c; k++) m *= z;
        row[dst[t]] += m;
    }
    for (int j = 0; j < nout; j++) row[j] *= ns[j];
}

// ---------------------------------------------------------------------------
// kernel_launch: graph-capturable, allocation-free.
// Input order (metadata): xyz, clm_tuvs, ns_lms, dst_pointers, xpows, ypows,
// zpows, max_l. Output: [N, 49] fp32.
// ---------------------------------------------------------------------------
extern "C" void kernel_launch(void* const* d_in, const int* in_sizes, int n_in,
                              void* d_out, int out_size) {
    const float* xyz = (const float*)d_in[0];
    const float* clm = (const float*)d_in[1];
    const float* ns  = (const float*)d_in[2];
    const int*   dst = (const int*)d_in[3];
    const int*   px  = (const int*)d_in[4];
    const int*   py  = (const int*)d_in[5];
    const int*   pz  = (const int*)d_in[6];

    const int N = in_sizes[0] / 3;
    float* out = (float*)d_out;

    const int T    = in_sizes[1];
    const int nout = in_sizes[2];

    if (T == TMAX && nout == NOUT && out_size == N * NOUT) {
        const int grid = (N + BS - 1) / BS;
        rsh_fast_kernel<<<grid, BS>>>(xyz, ns, out, N);
    } else {
        const int threads = 256;
        const int grid = (N + threads - 1) / threads;
        rsh_generic_kernel<<<grid, threads>>>(xyz, clm, ns, dst, px, py, pz,
                                              out, N, T, nout);
    }
}

// round 2
// speedup vs baseline: 1.0756x; 1.0756x over previous
#include <cuda_runtime.h>
#include <cuda_bf16.h>

// ---------------------------------------------------------------------------
// Real solid harmonics (RSHxyz), max_l = 6, N points -> [N, 49] fp32.
//
// R2: ns_lms baked into compile-time coefficients (removes 49 LDS + 49 FMUL
// per thread), per-warp smem staging with __syncwarp only (no block barrier),
// fully unrolled float4 flush per warp.
// ---------------------------------------------------------------------------

#define HDC __host__ __device__ constexpr

constexpr int MAXL = 6;
constexpr int NOUT = (MAXL + 1) * (MAXL + 1);   // 49
constexpr int TMAX = 188;                       // term count for max_l = 6
constexpr int BS   = 128;                       // block size (points per block)

struct Tables {
    int   dst[TMAX + 1];
    float clm[TMAX + 1];                        // clm * ns[dst]  (ns baked in)
    int   px[TMAX + 1], py[TMAX + 1], pz[TMAX + 1];
    int   count;
};

HDC double cfact(int n) { double r = 1.0; for (int i = 2; i <= n; i++) r *= (double)i; return r; }
HDC double ccomb(int n, int k) {
    return (k < 0 || k > n) ? 0.0 : cfact(n) / (cfact(k) * cfact(n - k));
}
// constexpr sqrt via Newton (converges to ~1 ulp; args are exact integers/2).
HDC double csqrt(double x) {
    double g = x > 1.0 ? x : 1.0;
    for (int i = 0; i < 100; i++) g = 0.5 * (g + x / g);
    return g;
}

// ns_lm = 1/(2^|m| l!) * sqrt(2 (l+|m|)! (l-|m|)! / (2 if m==0 else 1))
HDC double ns_lm(int l, int m) {
    int am = m < 0 ? -m : m;
    double p2 = 1.0; for (int q = 0; q < am; q++) p2 *= 2.0;
    return 1.0 / (p2 * cfact(l))
         * csqrt(2.0 * cfact(l + am) * cfact(l - am) / (m == 0 ? 2.0 : 1.0));
}

// Exact replica of the reference _build_coeffs loop structure; dst is
// monotone non-decreasing so each output's terms are contiguous.
HDC Tables build_tables() {
    Tables tb{};
    int idx = 0;
    for (int l = 0; l <= MAXL; l++) {
        for (int m = -l; m <= l; m++) {
            int am  = (m < 0) ? -m : m;
            int v2s = (m < 0) ? 1 : 0;
            int v2e = 2 * ((m < 0) ? ((am - 1) / 2) : (am / 2)) + v2s;
            // NOTE: reference rounds clm and ns to f32 separately, then
            // multiplies in f32. We replicate: (float)c * (float)ns.
            float nsf = (float)ns_lm(l, m);
            for (int t = 0; t <= (l - am) / 2; t++) {
                for (int u = 0; u <= t; u++) {
                    for (int v2 = v2s; v2 <= v2e; v2 += 2) {
                        int par = (t + (v2 - v2s) / 2) & 1;
                        double c = par ? -1.0 : 1.0;
                        for (int q = 0; q < t; q++) c *= 0.25;
                        c *= ccomb(l, t);
                        c *= (am + t <= l - t) ? ccomb(l - t, am + t) : 0.0;
                        c *= ccomb(t, u);
                        c *= (v2 <= am) ? ccomb(am, v2) : 0.0;
                        tb.dst[idx] = l * (l + 1) + m;
                        tb.clm[idx] = (float)c * nsf;
                        tb.px[idx]  = 2 * t + am - 2 * u - v2;
                        tb.py[idx]  = 2 * u + v2;
                        tb.pz[idx]  = l - 2 * t - am;
                        idx++;
                    }
                }
            }
        }
    }
    tb.count = idx;
    return tb;
}

static_assert(build_tables().count == TMAX, "term count mismatch for max_l=6");

struct TermInfo { int d, px, py, pz; float c; bool last; };

HDC TermInfo term_at(int t) {
    Tables tb = build_tables();
    TermInfo r{};
    r.d  = tb.dst[t];
    r.c  = tb.clm[t];
    r.px = tb.px[t];
    r.py = tb.py[t];
    r.pz = tb.pz[t];
    r.last = (t + 1 >= tb.count) || (tb.dst[t + 1] != tb.dst[t]);
    return r;
}

// Fully-unrolled term evaluation; all coefficients are immediates, monomial
// products get CSE'd by ptxas. One scalar STS per completed output.
template <int t>
__device__ __forceinline__ void eval_terms(const float (&xs)[MAXL + 1],
                                           const float (&ys)[MAXL + 1],
                                           const float (&zs)[MAXL + 1],
                                           float& acc,
                                           float* __restrict__ row_buf) {
    if constexpr (t < TMAX) {
        constexpr TermInfo TI = term_at(t);
        acc = fmaf(TI.c, xs[TI.px] * ys[TI.py] * zs[TI.pz], acc);
        if constexpr (TI.last) {
            row_buf[TI.d] = acc;
            acc = 0.0f;
        }
        eval_terms<t + 1>(xs, ys, zs, acc, row_buf);
    }
}

__global__ void __launch_bounds__(BS)
rsh_fast_kernel(const float* __restrict__ xyz,
                float* __restrict__ out, int N) {
    __shared__ __align__(16) float sbuf[BS * NOUT];

    const int tid  = threadIdx.x;
    const int base = blockIdx.x * BS;
    const int i    = base + tid;

    float x = 0.0f, y = 0.0f, z = 0.0f;
    if (i < N) {
        x = xyz[3 * i + 0];
        y = xyz[3 * i + 1];
        z = xyz[3 * i + 2];
    }

    // Power tables by repeated multiply (matches reference _pow_table
    // including 0^0 == 1 exactly).
    float xs[MAXL + 1], ys[MAXL + 1], zs[MAXL + 1];
    xs[0] = 1.0f; ys[0] = 1.0f; zs[0] = 1.0f;
#pragma unroll
    for (int k = 1; k <= MAXL; k++) {
        xs[k] = xs[k - 1] * x;
        ys[k] = ys[k - 1] * y;
        zs[k] = zs[k - 1] * z;
    }

    float acc = 0.0f;
    // Row stride 49 is coprime with 32 -> conflict-free scalar STS.
    eval_terms<0>(xs, ys, zs, acc, sbuf + tid * NOUT);

    // Per-warp flush: no block barrier. Each warp owns a contiguous
    // 32*49 = 1568-float (6272 B, 16B-aligned) slice of sbuf and of out.
    __syncwarp();

    const int wid   = tid >> 5;
    const int lane  = tid & 31;
    const int wbase = base + wid * 32;          // first point of this warp
    int wvalid = N - wbase;
    if (wvalid <= 0) return;
    if (wvalid > 32) wvalid = 32;

    const float* swarp = sbuf + wid * 32 * NOUT;
    float*       gwarp = out + (size_t)wbase * NOUT;

    if (wvalid == 32) {
        // 1568 floats = 392 float4 = 12*32 + 8
        const float4* s4 = reinterpret_cast<const float4*>(swarp);
        float4*       g4 = reinterpret_cast<float4*>(gwarp);
#pragma unroll
        for (int k = 0; k < 12; k++) g4[lane + 32 * k] = s4[lane + 32 * k];
        if (lane < 8) g4[384 + lane] = s4[384 + lane];
    } else {
        const int total = wvalid * NOUT;
        for (int k = lane; k < total; k += 32) gwarp[k] = swarp[k];
    }
}

// ---------------------------------------------------------------------------
// Generic fallback (only if runtime shapes don't match max_l=6 tables).
// ---------------------------------------------------------------------------
__global__ void rsh_generic_kernel(const float* __restrict__ xyz,
                                   const float* __restrict__ clm,
                                   const float* __restrict__ ns,
                                   const int* __restrict__ dst,
                                   const int* __restrict__ px,
                                   const int* __restrict__ py,
                                   const int* __restrict__ pz,
                                   float* __restrict__ out,
                                   int N, int T, int nout) {
    int i = blockIdx.x * blockDim.x + threadIdx.x;
    if (i >= N) return;
    float x = xyz[3 * i + 0], y = xyz[3 * i + 1], z = xyz[3 * i + 2];
    float* row = out + (size_t)i * nout;
    for (int j = 0; j < nout; j++) row[j] = 0.0f;
    for (int t = 0; t < T; t++) {
        float m = clm[t];
        int a = px[t], b = py[t], c = pz[t];
        for (int k = 0; k < a; k++) m *= x;
        for (int k = 0; k < b; k++) m *= y;
        for (int k = 0; k < c; k++) m *= z;
        row[dst[t]] += m;
    }
    for (int j = 0; j < nout; j++) row[j] *= ns[j];
}

extern "C" void kernel_launch(void* const* d_in, const int* in_sizes, int n_in,
                              void* d_out, int out_size) {
    const float* xyz = (const float*)d_in[0];
    const float* clm = (const float*)d_in[1];
    const float* ns  = (const float*)d_in[2];
    const int*   dst = (const int*)d_in[3];
    const int*   px  = (const int*)d_in[4];
    const int*   py  = (const int*)d_in[5];
    const int*   pz  = (const int*)d_in[6];

    const int N = in_sizes[0] / 3;
    float* out = (float*)d_out;

    const int T    = in_sizes[1];
    const int nout = in_sizes[2];

    if (T == TMAX && nout == NOUT && out_size == N * NOUT) {
        const int grid = (N + BS - 1) / BS;
        rsh_fast_kernel<<<grid, BS>>>(xyz, out, N);
    } else {
        const int threads = 256;
        const int grid = (N + threads - 1) / threads;
        rsh_generic_kernel<<<grid, threads>>>(xyz, clm, ns, dst, px, py, pz,
                                              out, N, T, nout);
    }
}

// round 3
// speedup vs baseline: 1.0804x; 1.0045x over previous
#include <cuda_runtime.h>
#include <cuda_bf16.h>
#include <cstdint>

// ---------------------------------------------------------------------------
// Real solid harmonics (RSHxyz), max_l = 6, N points -> [N, 49] fp32.
//
// R3: per-warp TMA bulk store (cp.async.bulk.global.shared::cta) replaces the
// LDS+STG flush — smem staging becomes write-only from the SM's perspective.
// Coefficients (clm * ns) baked at compile time; 188-term polynomial fully
// unrolled with immediate coefficients.
// ---------------------------------------------------------------------------

#define HDC __host__ __device__ constexpr

constexpr int MAXL = 6;
constexpr int NOUT = (MAXL + 1) * (MAXL + 1);   // 49
constexpr int TMAX = 188;                       // term count for max_l = 6
constexpr int BS   = 128;                       // block size (points per block)

struct Tables {
    int   dst[TMAX + 1];
    float clm[TMAX + 1];                        // clm * ns[dst]  (ns baked in)
    int   px[TMAX + 1], py[TMAX + 1], pz[TMAX + 1];
    int   count;
};

HDC double cfact(int n) { double r = 1.0; for (int i = 2; i <= n; i++) r *= (double)i; return r; }
HDC double ccomb(int n, int k) {
    return (k < 0 || k > n) ? 0.0 : cfact(n) / (cfact(k) * cfact(n - k));
}
HDC double csqrt(double x) {
    double g = x > 1.0 ? x : 1.0;
    for (int i = 0; i < 100; i++) g = 0.5 * (g + x / g);
    return g;
}
HDC double ns_lm(int l, int m) {
    int am = m < 0 ? -m : m;
    double p2 = 1.0; for (int q = 0; q < am; q++) p2 *= 2.0;
    return 1.0 / (p2 * cfact(l))
         * csqrt(2.0 * cfact(l + am) * cfact(l - am) / (m == 0 ? 2.0 : 1.0));
}

HDC Tables build_tables() {
    Tables tb{};
    int idx = 0;
    for (int l = 0; l <= MAXL; l++) {
        for (int m = -l; m <= l; m++) {
            int am  = (m < 0) ? -m : m;
            int v2s = (m < 0) ? 1 : 0;
            int v2e = 2 * ((m < 0) ? ((am - 1) / 2) : (am / 2)) + v2s;
            float nsf = (float)ns_lm(l, m);   // f32 round of ns, then f32 mul
            for (int t = 0; t <= (l - am) / 2; t++) {
                for (int u = 0; u <= t; u++) {
                    for (int v2 = v2s; v2 <= v2e; v2 += 2) {
                        int par = (t + (v2 - v2s) / 2) & 1;
                        double c = par ? -1.0 : 1.0;
                        for (int q = 0; q < t; q++) c *= 0.25;
                        c *= ccomb(l, t);
                        c *= (am + t <= l - t) ? ccomb(l - t, am + t) : 0.0;
                        c *= ccomb(t, u);
                        c *= (v2 <= am) ? ccomb(am, v2) : 0.0;
                        tb.dst[idx] = l * (l + 1) + m;
                        tb.clm[idx] = (float)c * nsf;
                        tb.px[idx]  = 2 * t + am - 2 * u - v2;
                        tb.py[idx]  = 2 * u + v2;
                        tb.pz[idx]  = l - 2 * t - am;
                        idx++;
                    }
                }
            }
        }
    }
    tb.count = idx;
    return tb;
}

static_assert(build_tables().count == TMAX, "term count mismatch for max_l=6");

struct TermInfo { int d, px, py, pz; float c; bool last; };

HDC TermInfo term_at(int t) {
    Tables tb = build_tables();
    TermInfo r{};
    r.d  = tb.dst[t];
    r.c  = tb.clm[t];
    r.px = tb.px[t];
    r.py = tb.py[t];
    r.pz = tb.pz[t];
    r.last = (t + 1 >= tb.count) || (tb.dst[t + 1] != tb.dst[t]);
    return r;
}

template <int t>
__device__ __forceinline__ void eval_terms(const float (&xs)[MAXL + 1],
                                           const float (&ys)[MAXL + 1],
                                           const float (&zs)[MAXL + 1],
                                           float& acc,
                                           float* __restrict__ row_buf) {
    if constexpr (t < TMAX) {
        constexpr TermInfo TI = term_at(t);
        acc = fmaf(TI.c, xs[TI.px] * ys[TI.py] * zs[TI.pz], acc);
        if constexpr (TI.last) {
            row_buf[TI.d] = acc;
            acc = 0.0f;
        }
        eval_terms<t + 1>(xs, ys, zs, acc, row_buf);
    }
}

__device__ __forceinline__ uint32_t smem_u32(const void* p) {
    uint32_t a;
    asm("{ .reg .u64 t; cvta.to.shared.u64 t, %1; cvt.u32.u64 %0, t; }"
        : "=r"(a) : "l"(p));
    return a;
}

__global__ void __launch_bounds__(BS)
rsh_fast_kernel(const float* __restrict__ xyz,
                float* __restrict__ out, int N) {
    __shared__ __align__(16) float sbuf[BS * NOUT];

    const int tid  = threadIdx.x;
    const int base = blockIdx.x * BS;
    const int i    = base + tid;

    float x = 0.0f, y = 0.0f, z = 0.0f;
    if (i < N) {
        x = xyz[3 * i + 0];
        y = xyz[3 * i + 1];
        z = xyz[3 * i + 2];
    }

    // Power tables by repeated multiply (matches reference _pow_table,
    // including 0^0 == 1 exactly).
    float xs[MAXL + 1], ys[MAXL + 1], zs[MAXL + 1];
    xs[0] = 1.0f; ys[0] = 1.0f; zs[0] = 1.0f;
#pragma unroll
    for (int k = 1; k <= MAXL; k++) {
        xs[k] = xs[k - 1] * x;
        ys[k] = ys[k - 1] * y;
        zs[k] = zs[k - 1] * z;
    }

    float acc = 0.0f;
    // Row stride 49 is coprime with 32 -> conflict-free scalar STS, and the
    // smem image is byte-identical to the output layout (no padding).
    eval_terms<0>(xs, ys, zs, acc, sbuf + tid * NOUT);

    __syncwarp();

    const int wid   = tid >> 5;
    const int lane  = tid & 31;
    const int wbase = base + wid * 32;          // first point of this warp
    int wvalid = N - wbase;
    if (wvalid <= 0) return;
    if (wvalid > 32) wvalid = 32;

    const float* swarp = sbuf + wid * 32 * NOUT;
    float*       gwarp = out + (size_t)wbase * NOUT;

    if (wvalid == 32) {
        // One TMA bulk store: 32*49*4 = 6272 B (16B-multiple), both src and
        // dst 16B-aligned. Issued by one lane; smem is never read by the SM.
        if (lane == 0) {
            // Order the warp's generic-proxy STS before the async-proxy read.
            asm volatile("fence.proxy.async.shared::cta;" ::: "memory");
            uint32_t s = smem_u32(swarp);
            asm volatile(
                "cp.async.bulk.global.shared::cta.bulk_group [%0], [%1], %2;"
                :: "l"(gwarp), "r"(s), "r"(32 * NOUT * 4) : "memory");
            asm volatile("cp.async.bulk.commit_group;" ::: "memory");
            asm volatile("cp.async.bulk.wait_group 0;" ::: "memory");
        }
    } else {
        const int total = wvalid * NOUT;
        for (int k = lane; k < total; k += 32) gwarp[k] = swarp[k];
    }
}

// ---------------------------------------------------------------------------
// Generic fallback (only if runtime shapes don't match max_l=6 tables).
// ---------------------------------------------------------------------------
__global__ void rsh_generic_kernel(const float* __restrict__ xyz,
                                   const float* __restrict__ clm,
                                   const float* __restrict__ ns,
                                   const int* __restrict__ dst,
                                   const int* __restrict__ px,
                                   const int* __restrict__ py,
                                   const int* __restrict__ pz,
                                   float* __restrict__ out,
                                   int N, int T, int nout) {
    int i = blockIdx.x * blockDim.x + threadIdx.x;
    if (i >= N) return;
    float x = xyz[3 * i + 0], y = xyz[3 * i + 1], z = xyz[3 * i + 2];
    float* row = out + (size_t)i * nout;
    for (int j = 0; j < nout; j++) row[j] = 0.0f;
    for (int t = 0; t < T; t++) {
        float m = clm[t];
        int a = px[t], b = py[t], c = pz[t];
        for (int k = 0; k < a; k++) m *= x;
        for (int k = 0; k < b; k++) m *= y;
        for (int k = 0; k < c; k++) m *= z;
        row[dst[t]] += m;
    }
    for (int j = 0; j < nout; j++) row[j] *= ns[j];
}

extern "C" void kernel_launch(void* const* d_in, const int* in_sizes, int n_in,
                              void* d_out, int out_size) {
    const float* xyz = (const float*)d_in[0];
    const float* clm = (const float*)d_in[1];
    const float* ns  = (const float*)d_in[2];
    const int*   dst = (const int*)d_in[3];
    const int*   px  = (const int*)d_in[4];
    const int*   py  = (const int*)d_in[5];
    const int*   pz  = (const int*)d_in[6];

    const int N = in_sizes[0] / 3;
    float* out = (float*)d_out;

    const int T    = in_sizes[1];
    const int nout = in_sizes[2];

    if (T == TMAX && nout == NOUT && out_size == N * NOUT) {
        const int grid = (N + BS - 1) / BS;
        rsh_fast_kernel<<<grid, BS>>>(xyz, out, N);
    } else {
        const int threads = 256;
        const int grid = (N + threads - 1) / threads;
        rsh_generic_kernel<<<grid, threads>>>(xyz, clm, ns, dst, px, py, pz,
                                              out, N, T, nout);
    }
}

// round 4
// speedup vs baseline: 1.0852x; 1.0045x over previous
#include <cuda_runtime.h>
#include <cuda_bf16.h>
#include <cstdint>

// ---------------------------------------------------------------------------
// Real solid harmonics (RSHxyz), max_l = 6, N points -> [N, 49] fp32.
//
// R4: 2 points per thread with interleaved FMA chains (2x ILP), 64-thread
// blocks, one 12.5KB TMA bulk store per warp (64 contiguous points).
// Coefficients (clm * ns) baked at compile time; fully unrolled polynomial.
// ---------------------------------------------------------------------------

#define HDC __host__ __device__ constexpr

constexpr int MAXL = 6;
constexpr int NOUT = (MAXL + 1) * (MAXL + 1);   // 49
constexpr int TMAX = 188;                       // term count for max_l = 6
constexpr int BS   = 64;                        // threads per block
constexpr int PPW  = 64;                        // points per warp
constexpr int PPB  = 128;                       // points per block

struct Tables {
    int   dst[TMAX + 1];
    float clm[TMAX + 1];                        // clm * ns[dst]  (ns baked in)
    int   px[TMAX + 1], py[TMAX + 1], pz[TMAX + 1];
    int   count;
};

HDC double cfact(int n) { double r = 1.0; for (int i = 2; i <= n; i++) r *= (double)i; return r; }
HDC double ccomb(int n, int k) {
    return (k < 0 || k > n) ? 0.0 : cfact(n) / (cfact(k) * cfact(n - k));
}
HDC double csqrt(double x) {
    double g = x > 1.0 ? x : 1.0;
    for (int i = 0; i < 100; i++) g = 0.5 * (g + x / g);
    return g;
}
HDC double ns_lm(int l, int m) {
    int am = m < 0 ? -m : m;
    double p2 = 1.0; for (int q = 0; q < am; q++) p2 *= 2.0;
    return 1.0 / (p2 * cfact(l))
         * csqrt(2.0 * cfact(l + am) * cfact(l - am) / (m == 0 ? 2.0 : 1.0));
}

HDC Tables build_tables() {
    Tables tb{};
    int idx = 0;
    for (int l = 0; l <= MAXL; l++) {
        for (int m = -l; m <= l; m++) {
            int am  = (m < 0) ? -m : m;
            int v2s = (m < 0) ? 1 : 0;
            int v2e = 2 * ((m < 0) ? ((am - 1) / 2) : (am / 2)) + v2s;
            float nsf = (float)ns_lm(l, m);   // f32 round of ns, then f32 mul
            for (int t = 0; t <= (l - am) / 2; t++) {
                for (int u = 0; u <= t; u++) {
                    for (int v2 = v2s; v2 <= v2e; v2 += 2) {
                        int par = (t + (v2 - v2s) / 2) & 1;
                        double c = par ? -1.0 : 1.0;
                        for (int q = 0; q < t; q++) c *= 0.25;
                        c *= ccomb(l, t);
                        c *= (am + t <= l - t) ? ccomb(l - t, am + t) : 0.0;
                        c *= ccomb(t, u);
                        c *= (v2 <= am) ? ccomb(am, v2) : 0.0;
                        tb.dst[idx] = l * (l + 1) + m;
                        tb.clm[idx] = (float)c * nsf;
                        tb.px[idx]  = 2 * t + am - 2 * u - v2;
                        tb.py[idx]  = 2 * u + v2;
                        tb.pz[idx]  = l - 2 * t - am;
                        idx++;
                    }
                }
            }
        }
    }
    tb.count = idx;
    return tb;
}

static_assert(build_tables().count == TMAX, "term count mismatch for max_l=6");

struct TermInfo { int d, px, py, pz; float c; bool last; };

HDC TermInfo term_at(int t) {
    Tables tb = build_tables();
    TermInfo r{};
    r.d  = tb.dst[t];
    r.c  = tb.clm[t];
    r.px = tb.px[t];
    r.py = tb.py[t];
    r.pz = tb.pz[t];
    r.last = (t + 1 >= tb.count) || (tb.dst[t + 1] != tb.dst[t]);
    return r;
}

// Two independent points advanced in lock-step: interleaved FMA chains give
// 2x ILP per thread without extra instruction-stream overhead.
template <int t>
__device__ __forceinline__ void eval_terms2(const float (&xa)[MAXL + 1],
                                            const float (&ya)[MAXL + 1],
                                            const float (&za)[MAXL + 1],
                                            const float (&xb)[MAXL + 1],
                                            const float (&yb)[MAXL + 1],
                                            const float (&zb)[MAXL + 1],
                                            float& accA, float& accB,
                                            float* __restrict__ rowA,
                                            float* __restrict__ rowB) {
    if constexpr (t < TMAX) {
        constexpr TermInfo TI = term_at(t);
        accA = fmaf(TI.c, xa[TI.px] * ya[TI.py] * za[TI.pz], accA);
        accB = fmaf(TI.c, xb[TI.px] * yb[TI.py] * zb[TI.pz], accB);
        if constexpr (TI.last) {
            rowA[TI.d] = accA;
            rowB[TI.d] = accB;
            accA = 0.0f;
            accB = 0.0f;
        }
        eval_terms2<t + 1>(xa, ya, za, xb, yb, zb, accA, accB, rowA, rowB);
    }
}

__device__ __forceinline__ uint32_t smem_u32(const void* p) {
    uint32_t a;
    asm("{ .reg .u64 t; cvta.to.shared.u64 t, %1; cvt.u32.u64 %0, t; }"
        : "=r"(a) : "l"(p));
    return a;
}

__global__ void __launch_bounds__(BS, 8)
rsh_fast_kernel(const float* __restrict__ xyz,
                float* __restrict__ out, int N) {
    __shared__ __align__(16) float sbuf[PPB * NOUT];   // 25088 B

    const int tid   = threadIdx.x;
    const int wid   = tid >> 5;
    const int lane  = tid & 31;
    const int wbase = blockIdx.x * PPB + wid * PPW;    // warp's first point
    const int p0    = wbase + lane;                    // local row: lane
    const int p1    = p0 + 32;                         // local row: lane+32

    float x0 = 0.f, y0 = 0.f, z0 = 0.f, x1 = 0.f, y1 = 0.f, z1 = 0.f;
    if (p0 < N) { x0 = xyz[3 * p0]; y0 = xyz[3 * p0 + 1]; z0 = xyz[3 * p0 + 2]; }
    if (p1 < N) { x1 = xyz[3 * p1]; y1 = xyz[3 * p1 + 1]; z1 = xyz[3 * p1 + 2]; }

    // Power tables by repeated multiply (matches reference _pow_table,
    // including 0^0 == 1 exactly).
    float xa[MAXL + 1], ya[MAXL + 1], za[MAXL + 1];
    float xb[MAXL + 1], yb[MAXL + 1], zb[MAXL + 1];
    xa[0] = ya[0] = za[0] = 1.0f;
    xb[0] = yb[0] = zb[0] = 1.0f;
#pragma unroll
    for (int k = 1; k <= MAXL; k++) {
        xa[k] = xa[k - 1] * x0; ya[k] = ya[k - 1] * y0; za[k] = za[k - 1] * z0;
        xb[k] = xb[k - 1] * x1; yb[k] = yb[k - 1] * y1; zb[k] = zb[k - 1] * z1;
    }

    float* swarp = sbuf + wid * PPW * NOUT;
    float accA = 0.0f, accB = 0.0f;
    // Row stride 49 (odd) -> conflict-free scalar STS for both halves; the
    // warp's smem image is byte-identical to out[wbase*49 ...].
    eval_terms2<0>(xa, ya, za, xb, yb, zb, accA, accB,
                   swarp + lane * NOUT, swarp + (lane + 32) * NOUT);

    __syncwarp();

    int wvalid = N - wbase;
    if (wvalid <= 0) return;
    if (wvalid > PPW) wvalid = PPW;

    float* gwarp = out + (size_t)wbase * NOUT;

    if (wvalid == PPW) {
        // One TMA bulk store: 64*49*4 = 12544 B (16B multiple, both sides
        // 16B-aligned). SM never reads the staging buffer.
        if (lane == 0) {
            asm volatile("fence.proxy.async.shared::cta;" ::: "memory");
            uint32_t s = smem_u32(swarp);
            asm volatile(
                "cp.async.bulk.global.shared::cta.bulk_group [%0], [%1], %2;"
                :: "l"(gwarp), "r"(s), "r"(PPW * NOUT * 4) : "memory");
            asm volatile("cp.async.bulk.commit_group;" ::: "memory");
            asm volatile("cp.async.bulk.wait_group 0;" ::: "memory");
        }
    } else {
        const int total = wvalid * NOUT;
        for (int k = lane; k < total; k += 32) gwarp[k] = swarp[k];
    }
}

// ---------------------------------------------------------------------------
// Generic fallback (only if runtime shapes don't match max_l=6 tables).
// ---------------------------------------------------------------------------
__global__ void rsh_generic_kernel(const float* __restrict__ xyz,
                                   const float* __restrict__ clm,
                                   const float* __restrict__ ns,
                                   const int* __restrict__ dst,
                                   const int* __restrict__ px,
                                   const int* __restrict__ py,
                                   const int* __restrict__ pz,
                                   float* __restrict__ out,
                                   int N, int T, int nout) {
    int i = blockIdx.x * blockDim.x + threadIdx.x;
    if (i >= N) return;
    float x = xyz[3 * i + 0], y = xyz[3 * i + 1], z = xyz[3 * i + 2];
    float* row = out + (size_t)i * nout;
    for (int j = 0; j < nout; j++) row[j] = 0.0f;
    for (int t = 0; t < T; t++) {
        float m = clm[t];
        int a = px[t], b = py[t], c = pz[t];
        for (int k = 0; k < a; k++) m *= x;
        for (int k = 0; k < b; k++) m *= y;
        for (int k = 0; k < c; k++) m *= z;
        row[dst[t]] += m;
    }
    for (int j = 0; j < nout; j++) row[j] *= ns[j];
}

extern "C" void kernel_launch(void* const* d_in, const int* in_sizes, int n_in,
                              void* d_out, int out_size) {
    const float* xyz = (const float*)d_in[0];
    const float* clm = (const float*)d_in[1];
    const float* ns  = (const float*)d_in[2];
    const int*   dst = (const int*)d_in[3];
    const int*   px  = (const int*)d_in[4];
    const int*   py  = (const int*)d_in[5];
    const int*   pz  = (const int*)d_in[6];

    const int N = in_sizes[0] / 3;
    float* out = (float*)d_out;

    const int T    = in_sizes[1];
    const int nout = in_sizes[2];

    if (T == TMAX && nout == NOUT && out_size == N * NOUT) {
        const int grid = (N + PPB - 1) / PPB;
        rsh_fast_kernel<<<grid, BS>>>(xyz, out, N);
    } else {
        const int threads = 256;
        const int grid = (N + threads - 1) / threads;
        rsh_generic_kernel<<<grid, threads>>>(xyz, clm, ns, dst, px, py, pz,
                                              out, N, T, nout);
    }
}